// round 2
// baseline (speedup 1.0000x reference)
#include <cuda_runtime.h>
#include <cstdint>

// Problem constants
#define B_DIM 32
#define W_DIM 16
#define N_DIM 256
#define D_DIM 256

// Materialized weight tensor: Wg[w][s][m][n], tf32-rounded fp32.
// 16*4*256*256 floats = 16.8 MB (L2-resident on GB300's 126MB L2).
__device__ float g_Wg[W_DIM * 4 * N_DIM * N_DIM];

__device__ __forceinline__ float to_tf32(float v) {
    float r;
    asm("cvt.rna.tf32.f32 %0, %1;" : "=f"(r) : "f"(v));
    return r;
}

__device__ __forceinline__ void mma_tf32(float* d, const float* a, const float* b) {
    const unsigned* A = reinterpret_cast<const unsigned*>(a);
    const unsigned* Bf = reinterpret_cast<const unsigned*>(b);
    asm volatile(
        "mma.sync.aligned.m16n8k8.row.col.f32.tf32.tf32.f32 "
        "{%0,%1,%2,%3},{%4,%5,%6,%7},{%8,%9},{%0,%1,%2,%3};"
        : "+f"(d[0]), "+f"(d[1]), "+f"(d[2]), "+f"(d[3])
        : "r"(A[0]), "r"(A[1]), "r"(A[2]), "r"(A[3]),
          "r"(Bf[0]), "r"(Bf[1]));
}

// ---------------------------------------------------------------------------
// Kernel 1: materialize Wg[w][s][m][n] = tf32(bias_table[rel_index[m][n], s*16+w])
// Coalesced 256B row reads of bias_table (via smem transpose), coalesced writes.
// ---------------------------------------------------------------------------
__global__ __launch_bounds__(256) void build_weights(
    const float* __restrict__ bias_table, const int* __restrict__ rel_index)
{
    __shared__ float tile[128][65];  // [n_local][c], pad 65 -> conflict-free transpose
    __shared__ int rels[128];
    const int m  = blockIdx.x;
    const int n0 = blockIdx.y * 128;
    const int tid = threadIdx.x;

    if (tid < 128) rels[tid] = rel_index[m * N_DIM + n0 + tid];
    __syncthreads();

    // Gather: full 64-float bias rows, coalesced (c fast-varying).
#pragma unroll
    for (int i = 0; i < 32; i++) {
        int u = tid + i * 256;        // 128 n * 64 c
        int n = u >> 6, c = u & 63;
        tile[n][c] = to_tf32(bias_table[rels[n] * 64 + c]);
    }
    __syncthreads();

    // Scatter to Wg planes: n fast-varying -> coalesced 512B stores per (c).
#pragma unroll
    for (int i = 0; i < 32; i++) {
        int u = tid + i * 256;
        int c = u >> 7, n = u & 127;
        int wq = c & 15, s = c >> 4;  // bias col c = s*16 + w
        g_Wg[(((wq * 4 + s) * N_DIM + m) << 8) + n0 + n] = tile[n][c];
    }
}

// ---------------------------------------------------------------------------
// Kernel 2: per-CTA (b, w, m_half) GEMM tile M=128 x D=256, K=256.
// tf32 mma.sync m16n8k8, double-buffered K-chunks of 32.
// SMEM layouts (all fragment LDS bank-conflict-free):
//   As[s][m 128][pitch 36]  (36 % 32 == 4  -> a-frag banks 4r+c distinct)
//   Xs[s][k 32][pitch 72]   (72 % 32 == 8  -> b-frag banks 8k+v distinct)
// ---------------------------------------------------------------------------
#define SA_PITCH 36
#define SA_PLANE (128 * SA_PITCH)      // 4608
#define SX_PITCH 72
#define SX_PLANE (32 * SX_PITCH)       // 2304
#define SA_TOTAL (4 * SA_PLANE)        // 18432
#define SX_TOTAL (4 * SX_PLANE)        // 9216
#define STAGE_F  (SA_TOTAL + SX_TOTAL) // 27648 floats = 108 KB

__global__ __launch_bounds__(512, 1) void pos_map_mm(
    const float* __restrict__ x, const float* __restrict__ token_bias,
    float* __restrict__ out)
{
    extern __shared__ float smem[];
    const int b  = blockIdx.x;
    const int w  = blockIdx.y;
    const int m0 = blockIdx.z * 128;
    const int tid  = threadIdx.x;
    const int lane = tid & 31, warp = tid >> 5;
    const int wm = warp & 3;   // 4 m-groups of 32 rows
    const int wd = warp >> 2;  // 4 d-groups of 16 v-cols

    const float*  Wbase = g_Wg + (size_t)(w * 4 * N_DIM + m0) * N_DIM; // +s*65536 +m*256 +n
    const float4* xbase = reinterpret_cast<const float4*>(
        x + (size_t)((b * W_DIM + w) * N_DIM) * D_DIM);

    float acc[2][2][4][4];
#pragma unroll
    for (int a = 0; a < 2; a++)
#pragma unroll
        for (int q = 0; q < 2; q++)
#pragma unroll
            for (int s = 0; s < 4; s++)
#pragma unroll
                for (int c = 0; c < 4; c++) acc[a][q][s][c] = 0.f;

    float4 xreg[4];

    // ---- prologue: chunk 0 into buffer 0 ----
    {
        float* As = smem;
#pragma unroll
        for (int i = 0; i < 8; i++) {
            int u = tid + i * 512;                    // 4096 x 16B units
            int s = u >> 10, m = (u >> 3) & 127, q = u & 7;
            const float* src = Wbase + s * 65536 + m * 256 + q * 4;
            unsigned sa = (unsigned)__cvta_generic_to_shared(
                As + s * SA_PLANE + m * SA_PITCH + q * 4);
            asm volatile("cp.async.cg.shared.global [%0], [%1], 16;\n"
                         :: "r"(sa), "l"(src));
        }
        asm volatile("cp.async.commit_group;\n");
#pragma unroll
        for (int i = 0; i < 4; i++) {
            int u = tid + i * 512;
            int k = u >> 6, vv = u & 63;
            xreg[i] = xbase[k * 64 + vv];
        }
        float* Xs = smem + SA_TOTAL;
#pragma unroll
        for (int i = 0; i < 4; i++) {
            int u = tid + i * 512;
            int k = u >> 6, vv = u & 63;
            Xs[(0 * 32 + k) * SX_PITCH + vv] = to_tf32(xreg[i].x);
            Xs[(1 * 32 + k) * SX_PITCH + vv] = to_tf32(xreg[i].y);
            Xs[(2 * 32 + k) * SX_PITCH + vv] = to_tf32(xreg[i].z);
            Xs[(3 * 32 + k) * SX_PITCH + vv] = to_tf32(xreg[i].w);
        }
        asm volatile("cp.async.wait_group 0;\n");
        __syncthreads();
    }

    // ---- main K loop: 8 chunks of 32 ----
    for (int ch = 0; ch < 8; ch++) {
        float* As  = smem + (ch & 1) * STAGE_F;
        float* Xs  = As + SA_TOTAL;
        float* Asn = smem + ((ch + 1) & 1) * STAGE_F;

        if (ch < 7) {
            int n0 = (ch + 1) * 32;
#pragma unroll
            for (int i = 0; i < 8; i++) {
                int u = tid + i * 512;
                int s = u >> 10, m = (u >> 3) & 127, q = u & 7;
                const float* src = Wbase + s * 65536 + m * 256 + n0 + q * 4;
                unsigned sa = (unsigned)__cvta_generic_to_shared(
                    Asn + s * SA_PLANE + m * SA_PITCH + q * 4);
                asm volatile("cp.async.cg.shared.global [%0], [%1], 16;\n"
                             :: "r"(sa), "l"(src));
            }
            asm volatile("cp.async.commit_group;\n");
#pragma unroll
            for (int i = 0; i < 4; i++) {
                int u = tid + i * 512;
                int k = u >> 6, vv = u & 63;
                xreg[i] = xbase[(n0 + k) * 64 + vv];
            }
        }

        // compute current chunk: 4 k-steps of 8
#pragma unroll
        for (int t = 0; t < 4; t++) {
            float bf[4][2][2];  // [s][vt][b0,b1]
            const int kk = (t << 3) + (lane & 3);
            const int vb = wd * 16 + (lane >> 2);
#pragma unroll
            for (int s = 0; s < 4; s++)
#pragma unroll
                for (int vt = 0; vt < 2; vt++) {
                    bf[s][vt][0] = Xs[(s * 32 + kk) * SX_PITCH + vb + vt * 8];
                    bf[s][vt][1] = Xs[(s * 32 + kk + 4) * SX_PITCH + vb + vt * 8];
                }
            const int r = lane >> 2, c = lane & 3;
#pragma unroll
            for (int s = 0; s < 4; s++) {
#pragma unroll
                for (int mt = 0; mt < 2; mt++) {
                    const float* Ab = As + s * SA_PLANE
                                      + (wm * 32 + mt * 16) * SA_PITCH + (t << 3);
                    float af[4];
                    af[0] = Ab[r * SA_PITCH + c];
                    af[1] = Ab[(r + 8) * SA_PITCH + c];
                    af[2] = Ab[r * SA_PITCH + c + 4];
                    af[3] = Ab[(r + 8) * SA_PITCH + c + 4];
#pragma unroll
                    for (int vt = 0; vt < 2; vt++)
                        mma_tf32(acc[mt][vt][s], af, bf[s][vt]);
                }
            }
        }

        if (ch < 7) {
            float* Xsn = Asn + SA_TOTAL;
#pragma unroll
            for (int i = 0; i < 4; i++) {
                int u = tid + i * 512;
                int k = u >> 6, vv = u & 63;
                Xsn[(0 * 32 + k) * SX_PITCH + vv] = to_tf32(xreg[i].x);
                Xsn[(1 * 32 + k) * SX_PITCH + vv] = to_tf32(xreg[i].y);
                Xsn[(2 * 32 + k) * SX_PITCH + vv] = to_tf32(xreg[i].z);
                Xsn[(3 * 32 + k) * SX_PITCH + vv] = to_tf32(xreg[i].w);
            }
        }
        asm volatile("cp.async.wait_group 0;\n");
        __syncthreads();
    }

    // ---- epilogue: add token bias, write out ----
#pragma unroll
    for (int mt = 0; mt < 2; mt++)
#pragma unroll
        for (int j = 0; j < 2; j++) {
            int m = m0 + wm * 32 + mt * 16 + (lane >> 2) + j * 8;
            float* orow = out + ((size_t)((b * W_DIM + w) * N_DIM + m) << 8);
#pragma unroll
            for (int s = 0; s < 4; s++) {
                float tb = token_bias[(w * 4 + s) * N_DIM + m];
#pragma unroll
                for (int vt = 0; vt < 2; vt++) {
                    int v = wd * 16 + vt * 8 + ((lane & 3) << 1);
                    orow[(v << 2) + s]       = acc[mt][vt][s][j * 2 + 0] + tb;
                    orow[((v + 1) << 2) + s] = acc[mt][vt][s][j * 2 + 1] + tb;
                }
            }
        }
}

// ---------------------------------------------------------------------------
// Launch: inputs in metadata order: x, bias_table, token_bias, rel_index
// ---------------------------------------------------------------------------
extern "C" void kernel_launch(void* const* d_in, const int* in_sizes, int n_in,
                              void* d_out, int out_size)
{
    const float* x          = (const float*)d_in[0];
    const float* bias_table = (const float*)d_in[1];
    const float* token_bias = (const float*)d_in[2];
    const int*   rel_index  = (const int*)d_in[3];
    float* out = (float*)d_out;

    (void)in_sizes; (void)n_in; (void)out_size;

    // 2 * 27648 floats = 221184 B dynamic smem (opt-in, < 227KB sm_103a cap)
    cudaFuncSetAttribute(pos_map_mm,
                         cudaFuncAttributeMaxDynamicSharedMemorySize,
                         2 * STAGE_F * (int)sizeof(float));

    build_weights<<<dim3(256, 2), 256>>>(bias_table, rel_index);
    pos_map_mm<<<dim3(B_DIM, W_DIM, 2), 512, 2 * STAGE_F * sizeof(float)>>>(
        x, token_bias, out);
}

// round 4
// speedup vs baseline: 2.1560x; 2.1560x over previous
#include <cuda_runtime.h>
#include <cuda_fp16.h>
#include <cstdint>

// ---------------------------------------------------------------------------
// Problem constants
// ---------------------------------------------------------------------------
#define B_DIM 32
#define W_DIM 16
#define N_DIM 256

// Materialized weight tensor: Wgh[w][s][m][n] in fp16. 8.4 MB, L2-resident.
__device__ __half g_Wgh[W_DIM * 4 * N_DIM * N_DIM];

// ---------------------------------------------------------------------------
// Kernel 1: Wgh[w][s][m][n] = fp16(bias_table[rel_index[m][n], s*16+w])
// ---------------------------------------------------------------------------
__global__ __launch_bounds__(256) void build_weights(
    const float* __restrict__ bias_table, const int* __restrict__ rel_index)
{
    __shared__ float tile[128][65];
    __shared__ int rels[128];
    const int m  = blockIdx.x;
    const int n0 = blockIdx.y * 128;
    const int tid = threadIdx.x;

    if (tid < 128) rels[tid] = rel_index[m * N_DIM + n0 + tid];
    __syncthreads();

#pragma unroll
    for (int i = 0; i < 32; i++) {
        int u = tid + i * 256;
        int n = u >> 6, c = u & 63;
        tile[n][c] = bias_table[rels[n] * 64 + c];
    }
    __syncthreads();

    // Scatter: per warp fixed c, n consecutive -> 64B coalesced half stores.
#pragma unroll
    for (int i = 0; i < 32; i++) {
        int u = tid + i * 256;
        int c = u >> 7, n = u & 127;
        int wq = c & 15, s = c >> 4;
        g_Wgh[(((wq * 4 + s) * N_DIM + m) << 8) + n0 + n] = __float2half_rn(tile[n][c]);
    }
}

// ---------------------------------------------------------------------------
// MMA / ldmatrix helpers
// ---------------------------------------------------------------------------
__device__ __forceinline__ void ldsm_x4(uint32_t* r, uint32_t addr) {
    asm volatile("ldmatrix.sync.aligned.m8n8.x4.shared.b16 {%0,%1,%2,%3}, [%4];"
        : "=r"(r[0]), "=r"(r[1]), "=r"(r[2]), "=r"(r[3]) : "r"(addr));
}
__device__ __forceinline__ void ldsm_x4_t(uint32_t* r, uint32_t addr) {
    asm volatile("ldmatrix.sync.aligned.m8n8.x4.trans.shared.b16 {%0,%1,%2,%3}, [%4];"
        : "=r"(r[0]), "=r"(r[1]), "=r"(r[2]), "=r"(r[3]) : "r"(addr));
}
__device__ __forceinline__ void hmma(float* d, const uint32_t* a, uint32_t b0, uint32_t b1) {
    asm volatile(
        "mma.sync.aligned.m16n8k16.row.col.f32.f16.f16.f32 "
        "{%0,%1,%2,%3},{%4,%5,%6,%7},{%8,%9},{%0,%1,%2,%3};"
        : "+f"(d[0]), "+f"(d[1]), "+f"(d[2]), "+f"(d[3])
        : "r"(a[0]), "r"(a[1]), "r"(a[2]), "r"(a[3]), "r"(b0), "r"(b1));
}
__device__ __forceinline__ uint32_t pack_h2(float lo, float hi) {
    __half2 h = __floats2half2_rn(lo, hi);
    return *reinterpret_cast<uint32_t*>(&h);
}
__device__ __forceinline__ uint32_t smem_u32(const void* p) {
    uint32_t a;
    asm("{ .reg .u64 t; cvta.to.shared.u64 t, %1; cvt.u32.u64 %0, t; }"
        : "=r"(a) : "l"(p));
    return a;
}

// ---------------------------------------------------------------------------
// Kernel 2: CTA=(b, w, m_half) computes OUT[128m, 256(v,s)] via fp16 mma.sync.
// K chunks of 32. SMEM stages (double buffered, XOR-swizzled, LDSM-friendly):
//   A: [s][m 128][32k] fp16, row 64B, chunk swizzle q ^= (m>>1)&3
//   X: [s][k 32][64v] fp16, row 128B, chunk swizzle c ^= k&7
// ---------------------------------------------------------------------------
#define AS_PLANE 8192
#define A_STAGE  32768
#define XS_PLANE 4096
#define X_STAGE  16384
#define STAGE_BYTES (A_STAGE + X_STAGE)        // 49152
#define OUT_PITCH 260
#define SMEM_DYN (128 * OUT_PITCH * 4)         // 133120 (> 2*STAGE_BYTES)

__global__ __launch_bounds__(512, 1) void pos_map_mm(
    const float* __restrict__ x, const float* __restrict__ token_bias,
    float* __restrict__ out)
{
    extern __shared__ __align__(16) char smem[];
    const int b = blockIdx.x, w = blockIdx.y, m0 = blockIdx.z * 128;
    const int tid = threadIdx.x, lane = tid & 31, warp = tid >> 5;
    const int wm = warp & 3;    // m-group: 32 rows
    const int wc = warp >> 2;   // s-plane: 64 v cols
    const uint32_t sbase = smem_u32(smem);

    const __half* WgBase = g_Wgh + (size_t)(w * 4) * 65536 + (size_t)m0 * 256;
    const float4* xb4 = (const float4*)x + (size_t)(b * 16 + w) * (256 * 64);

    float acc[2][8][4];
#pragma unroll
    for (int mt = 0; mt < 2; mt++)
#pragma unroll
        for (int nt = 0; nt < 8; nt++)
#pragma unroll
            for (int j = 0; j < 4; j++) acc[mt][nt][j] = 0.f;

    uint32_t xh[2][4];   // prefetched X for next chunk: [iter][s] half2

    // Per-lane LDSM geometry
    const int grp  = lane >> 3;             // 0..3
    const int row8 = (grp & 1) * 8 + (lane & 7);
    const int qsel = grp >> 1;              // 0/1

    // ---- helpers as lambdas ----
    auto issue_A = [&](int st, int n0c) {
#pragma unroll
        for (int i = 0; i < 4; i++) {
            int u = tid + i * 512;                 // 2048 x 16B
            int s = u >> 9, r = (u >> 2) & 127, q = u & 3;
            const __half* src = WgBase + s * 65536 + r * 256 + n0c + q * 8;
            uint32_t dst = sbase + st * STAGE_BYTES + s * AS_PLANE + r * 64
                         + ((q ^ ((r >> 1) & 3)) << 4);
            asm volatile("cp.async.cg.shared.global [%0], [%1], 16;"
                         :: "r"(dst), "l"(src));
        }
        asm volatile("cp.async.commit_group;");
    };
    auto load_X = [&](int n0c) {
#pragma unroll
        for (int it = 0; it < 2; it++) {
            int u = tid + it * 512;                // 1024 (k, vpair) units
            int vp = u & 31, k = u >> 5;
            float4 f0 = xb4[(n0c + k) * 64 + 2 * vp];
            float4 f1 = xb4[(n0c + k) * 64 + 2 * vp + 1];
            xh[it][0] = pack_h2(f0.x, f1.x);
            xh[it][1] = pack_h2(f0.y, f1.y);
            xh[it][2] = pack_h2(f0.z, f1.z);
            xh[it][3] = pack_h2(f0.w, f1.w);
        }
    };
    auto store_X = [&](int st) {
        char* xs = smem + st * STAGE_BYTES + A_STAGE;
#pragma unroll
        for (int it = 0; it < 2; it++) {
            int u = tid + it * 512;
            int vp = u & 31, k = u >> 5;
            int off = k * 128 + (((vp >> 2) ^ (k & 7)) << 4) + ((vp & 3) << 2);
#pragma unroll
            for (int s = 0; s < 4; s++)
                *(uint32_t*)(xs + s * XS_PLANE + off) = xh[it][s];
        }
    };
    auto compute = [&](int st) {
        const uint32_t sA = sbase + st * STAGE_BYTES + wc * AS_PLANE;
        const uint32_t sX = sbase + st * STAGE_BYTES + A_STAGE + wc * XS_PLANE;
#pragma unroll
        for (int ks = 0; ks < 2; ks++) {
            uint32_t a[2][4];
#pragma unroll
            for (int mt = 0; mt < 2; mt++) {
                int m = wm * 32 + mt * 16 + row8;
                int q = ks * 2 + qsel;
                ldsm_x4(a[mt], sA + m * 64 + ((q ^ ((m >> 1) & 3)) << 4));
            }
            uint32_t bq[4][4];
#pragma unroll
            for (int ng = 0; ng < 4; ng++) {
                int k = ks * 16 + row8;
                int c = ng * 2 + qsel;
                ldsm_x4_t(bq[ng], sX + k * 128 + ((c ^ (k & 7)) << 4));
            }
#pragma unroll
            for (int mt = 0; mt < 2; mt++)
#pragma unroll
                for (int nt = 0; nt < 8; nt++)
                    hmma(acc[mt][nt], a[mt],
                         bq[nt >> 1][(nt & 1) * 2], bq[nt >> 1][(nt & 1) * 2 + 1]);
        }
    };

    // ---- prologue: chunk 0 ----
    issue_A(0, 0);
    load_X(0);
    store_X(0);
    asm volatile("cp.async.wait_group 0;");
    __syncthreads();

    // ---- main loop over 8 K-chunks ----
    for (int ch = 0; ch < 8; ch++) {
        const int st = ch & 1, nx = (ch + 1) & 1;
        if (ch < 7) {
            issue_A(nx, (ch + 1) * 32);
            load_X((ch + 1) * 32);
        }
        compute(st);
        if (ch < 7) store_X(nx);
        asm volatile("cp.async.wait_group 0;");
        __syncthreads();
    }

    // ---- epilogue: bias add, smem transpose, coalesced store ----
    float* so = (float*)smem;   // [128][OUT_PITCH]
#pragma unroll
    for (int mt = 0; mt < 2; mt++)
#pragma unroll
        for (int j = 0; j < 2; j++) {
            int m = wm * 32 + mt * 16 + (lane >> 2) + j * 8;
            float tb = token_bias[(w * 4 + wc) * 256 + m0 + m];
            float* dr = so + m * OUT_PITCH + wc;
#pragma unroll
            for (int nt = 0; nt < 8; nt++) {
                int v = nt * 8 + ((lane & 3) << 1);
                dr[v * 4]       = acc[mt][nt][j * 2 + 0] + tb;
                dr[(v + 1) * 4] = acc[mt][nt][j * 2 + 1] + tb;
            }
        }
    __syncthreads();

    float4* ob = (float4*)(out + (size_t)((b * 16 + w) * 256 + m0) * 256);
#pragma unroll
    for (int i = 0; i < 16; i++) {
        int u = tid + i * 512;
        int row = u >> 6, c = u & 63;
        ob[row * 64 + c] = *(float4*)(so + row * OUT_PITCH + c * 4);
    }
}

// ---------------------------------------------------------------------------
// Launch: inputs in metadata order: x, bias_table, token_bias, rel_index
// ---------------------------------------------------------------------------
extern "C" void kernel_launch(void* const* d_in, const int* in_sizes, int n_in,
                              void* d_out, int out_size)
{
    const float* x          = (const float*)d_in[0];
    const float* bias_table = (const float*)d_in[1];
    const float* token_bias = (const float*)d_in[2];
    const int*   rel_index  = (const int*)d_in[3];
    float* out = (float*)d_out;
    (void)in_sizes; (void)n_in; (void)out_size;

    cudaFuncSetAttribute(pos_map_mm,
                         cudaFuncAttributeMaxDynamicSharedMemorySize, SMEM_DYN);

    build_weights<<<dim3(256, 2), 256>>>(bias_table, rel_index);
    pos_map_mm<<<dim3(B_DIM, W_DIM, 2), 512, SMEM_DYN>>>(x, token_bias, out);
}